// round 1
// baseline (speedup 1.0000x reference)
#include <cuda_runtime.h>

namespace qc {

constexpr int NQ = 14;            // qubits
constexpr int NL = 4;             // layers
constexpr int NS = 1 << NQ;       // 16384 amplitudes
constexpr int NT = 512;           // threads per CTA
constexpr int NC = NQ - 1;        // 13 CNOT steps per layer
constexpr int NWARP = NT / 32;

// shared memory layout (float offsets)
constexpr int OFF_IM  = NS;                        // im[16384]
constexpr int OFF_U   = 2 * NS;                    // 56 gates * 8 floats
constexpr int OFF_EP  = OFF_U + NL * NQ * 8;       // 52 phases p (2 floats)
constexpr int OFF_EQ  = OFF_EP + NL * NC * 2;      // 52 phases q
constexpr int OFF_ENC = OFF_EQ + NL * NC * 2;      // 14 (c,s) encoding pairs
constexpr int OFF_RED = OFF_ENC + 2 * NQ;          // 16 warps * 14 partials
constexpr int SMEM_FLOATS = OFF_RED + NWARP * NQ;
constexpr int SMEM_BYTES  = SMEM_FLOATS * 4;       // ~134.7 KB

// XOR swizzle so all grouped sweeps are SMEM-bank-conflict-free
__device__ __forceinline__ int swz(int i) { return i ^ ((i >> 4) & 31); }

// Apply W fused 1-qubit gates (qubits S..S+W-1) in one sweep.
// usm: 8 floats per gate: u00.x u00.y u01.x u01.y u10.x u10.y u11.x u11.y
template<int S, int W>
__device__ __forceinline__ void sweep1q(float* __restrict__ re, float* __restrict__ im,
                                        const float* __restrict__ usm, int tid) {
  constexpr int M = 1 << W;
  float u[W][8];
#pragma unroll
  for (int j = 0; j < W; ++j)
#pragma unroll
    for (int e = 0; e < 8; ++e) u[j][e] = usm[j * 8 + e];

#pragma unroll
  for (int it = 0; it < (NS >> W) / NT; ++it) {
    const int g = tid + it * NT;
    const int base = ((g >> S) << (S + W)) | (g & ((1 << S) - 1));
    float vr[M], vi[M];
#pragma unroll
    for (int o = 0; o < M; ++o) {
      const int p = swz(base | (o << S));
      vr[o] = re[p]; vi[o] = im[p];
    }
#pragma unroll
    for (int j = 0; j < W; ++j) {
#pragma unroll
      for (int o = 0; o < M; ++o) {
        if (o & (1 << j)) continue;
        const int o1 = o | (1 << j);
        const float ar = vr[o], ai = vi[o], br = vr[o1], bi = vi[o1];
        vr[o]  = u[j][0]*ar - u[j][1]*ai + u[j][2]*br - u[j][3]*bi;
        vi[o]  = u[j][0]*ai + u[j][1]*ar + u[j][2]*bi + u[j][3]*br;
        vr[o1] = u[j][4]*ar - u[j][5]*ai + u[j][6]*br - u[j][7]*bi;
        vi[o1] = u[j][4]*ai + u[j][5]*ar + u[j][6]*bi + u[j][7]*br;
      }
    }
#pragma unroll
    for (int o = 0; o < M; ++o) {
      const int p = swz(base | (o << S));
      re[p] = vr[o]; im[p] = vi[o];
    }
  }
}

// Apply NST fused (CNOT(control=S+st, target=S+st+1); RZ(target)) steps in one sweep.
// psm/qsm: 2 floats per step: phase for target bit 0 / bit 1 (applied AFTER the flip).
template<int S, int W, int NST>
__device__ __forceinline__ void sweepCnot(float* __restrict__ re, float* __restrict__ im,
                                          const float* __restrict__ psm,
                                          const float* __restrict__ qsm, int tid) {
  constexpr int M = 1 << W;
  float pp[NST][2], qq[NST][2];
#pragma unroll
  for (int st = 0; st < NST; ++st) {
    pp[st][0] = psm[2*st]; pp[st][1] = psm[2*st + 1];
    qq[st][0] = qsm[2*st]; qq[st][1] = qsm[2*st + 1];
  }
#pragma unroll
  for (int it = 0; it < (NS >> W) / NT; ++it) {
    const int g = tid + it * NT;
    const int base = ((g >> S) << (S + W)) | (g & ((1 << S) - 1));
    float vr[M], vi[M];
#pragma unroll
    for (int o = 0; o < M; ++o) {
      const int p = swz(base | (o << S));
      vr[o] = re[p]; vi[o] = im[p];
    }
#pragma unroll
    for (int st = 0; st < NST; ++st) {
      const int tb = st + 1;   // local target bit
#pragma unroll
      for (int o = 0; o < M; ++o) {
        if (o & (1 << tb)) continue;
        const int o1 = o | (1 << tb);
        const bool ctrl = (o >> st) & 1;       // compile-time after unroll
        float ar, ai, br, bi;
        if (ctrl) { ar = vr[o1]; ai = vi[o1]; br = vr[o];  bi = vi[o];  } // flip target
        else      { ar = vr[o];  ai = vi[o];  br = vr[o1]; bi = vi[o1]; }
        vr[o]  = pp[st][0]*ar - pp[st][1]*ai;  // target=0 -> phase p
        vi[o]  = pp[st][0]*ai + pp[st][1]*ar;
        vr[o1] = qq[st][0]*br - qq[st][1]*bi;  // target=1 -> phase q
        vi[o1] = qq[st][0]*bi + qq[st][1]*br;
      }
    }
#pragma unroll
    for (int o = 0; o < M; ++o) {
      const int p = swz(base | (o << S));
      re[p] = vr[o]; im[p] = vi[o];
    }
  }
}

__global__ void __launch_bounds__(NT, 1)
qc_kernel(const float* __restrict__ x, const float* __restrict__ prx,
          const float* __restrict__ pry, const float* __restrict__ prz,
          const float* __restrict__ pent, float* __restrict__ out) {
  extern __shared__ float sm[];
  float* re = sm;
  float* im = sm + OFF_IM;
  const int tid = threadIdx.x;
  const int b = blockIdx.x;

  // ---- prologue: fused gate matrices U = Rz*Ry*Rx, entangle RZ phases, encoding ----
  if (tid < NL * NQ) {
    float cx, sx, cy, sy, cz, sz;
    sincosf(0.5f * prx[tid], &sx, &cx);
    sincosf(0.5f * pry[tid], &sy, &cy);
    sincosf(0.5f * prz[tid], &sz, &cz);
    // Ry*Rx
    const float r00x =  cy*cx, r00y =  sy*sx;
    const float r01x = -sy*cx, r01y = -cy*sx;
    const float r10x =  sy*cx, r10y = -cy*sx;
    const float r11x =  cy*cx, r11y = -sy*sx;
    // row0 *= (cz - i sz); row1 *= (cz + i sz)
    float* u = sm + OFF_U + tid * 8;
    u[0] = r00x*cz + r00y*sz;  u[1] = r00y*cz - r00x*sz;
    u[2] = r01x*cz + r01y*sz;  u[3] = r01y*cz - r01x*sz;
    u[4] = r10x*cz - r10y*sz;  u[5] = r10x*sz + r10y*cz;
    u[6] = r11x*cz - r11y*sz;  u[7] = r11x*sz + r11y*cz;
  }
  if (tid >= 64 && tid < 64 + NL * NC) {
    const int e = tid - 64;
    float c, s; sincosf(0.5f * pent[e], &s, &c);
    sm[OFF_EP + 2*e] = c; sm[OFF_EP + 2*e + 1] = -s;   // e^{-i t/2}
    sm[OFF_EQ + 2*e] = c; sm[OFF_EQ + 2*e + 1] =  s;   // e^{+i t/2}
  }
  if (tid >= 128 && tid < 128 + NQ) {
    const int i = tid - 128;
    const float th = 0.5f * 3.14159265358979323846f * tanhf(x[b * NQ + i]);
    float c, s; sincosf(th, &s, &c);
    sm[OFF_ENC + 2*i] = c; sm[OFF_ENC + 2*i + 1] = s;
  }
  __syncthreads();

  // ---- init: |0..0> + per-qubit RY encoding == product state ----
  {
    float ec[NQ], es[NQ];
#pragma unroll
    for (int i = 0; i < NQ; ++i) { ec[i] = sm[OFF_ENC + 2*i]; es[i] = sm[OFF_ENC + 2*i + 1]; }
#pragma unroll
    for (int k = 0; k < NS / NT; ++k) {
      const int idx = tid + k * NT;
      float pr = 1.0f;
#pragma unroll
      for (int i = 0; i < NQ; ++i) pr *= (idx & (1 << i)) ? es[i] : ec[i];
      const int p = swz(idx);
      re[p] = pr; im[p] = 0.0f;
    }
  }

  // ---- layers ----
  for (int l = 0; l < NL; ++l) {
    const float* ul = sm + OFF_U  + l * NQ * 8;
    const float* pl = sm + OFF_EP + l * NC * 2;
    const float* ql = sm + OFF_EQ + l * NC * 2;
    __syncthreads(); sweep1q<0, 4>(re, im, ul + 0 * 8, tid);
    __syncthreads(); sweep1q<4, 4>(re, im, ul + 4 * 8, tid);
    __syncthreads(); sweep1q<8, 4>(re, im, ul + 8 * 8, tid);
    __syncthreads(); sweep1q<12, 2>(re, im, ul + 12 * 8, tid);
    __syncthreads(); sweepCnot<0, 4, 3>(re, im, pl + 0,  ql + 0,  tid);
    __syncthreads(); sweepCnot<3, 4, 3>(re, im, pl + 6,  ql + 6,  tid);
    __syncthreads(); sweepCnot<6, 4, 3>(re, im, pl + 12, ql + 12, tid);
    __syncthreads(); sweepCnot<9, 4, 3>(re, im, pl + 18, ql + 18, tid);
    __syncthreads(); sweepCnot<12, 2, 1>(re, im, pl + 24, ql + 24, tid);
  }
  __syncthreads();

  // ---- measurement: <Z_q> = sum prob * (1 - 2*bit_q) ----
  float acc[NQ];
#pragma unroll
  for (int q = 0; q < NQ; ++q) acc[q] = 0.0f;
#pragma unroll
  for (int k = 0; k < NS / NT; ++k) {
    const int idx = tid + k * NT;
    const int p = swz(idx);
    const float rr = re[p], ii = im[p];
    const float pr = rr * rr + ii * ii;
#pragma unroll
    for (int q = 0; q < NQ; ++q) {
      if (idx & (1 << q)) acc[q] -= pr; else acc[q] += pr;
    }
  }
#pragma unroll
  for (int q = 0; q < NQ; ++q)
#pragma unroll
    for (int off = 16; off > 0; off >>= 1)
      acc[q] += __shfl_xor_sync(0xffffffffu, acc[q], off);
  const int warp = tid >> 5, lane = tid & 31;
  if (lane == 0) {
#pragma unroll
    for (int q = 0; q < NQ; ++q) sm[OFF_RED + warp * NQ + q] = acc[q];
  }
  __syncthreads();
  if (tid < NQ) {
    float s = 0.0f;
#pragma unroll
    for (int w = 0; w < NWARP; ++w) s += sm[OFF_RED + w * NQ + tid];
    out[b * NQ + tid] = s;
  }
}

} // namespace qc

extern "C" void kernel_launch(void* const* d_in, const int* in_sizes, int n_in,
                              void* d_out, int out_size) {
  const float* x    = (const float*)d_in[0];
  const float* prx  = (const float*)d_in[1];
  const float* pry  = (const float*)d_in[2];
  const float* prz  = (const float*)d_in[3];
  const float* pent = (const float*)d_in[4];
  float* out = (float*)d_out;
  const int batch = in_sizes[0] / qc::NQ;   // 128
  cudaFuncSetAttribute(qc::qc_kernel, cudaFuncAttributeMaxDynamicSharedMemorySize,
                       qc::SMEM_BYTES);
  qc::qc_kernel<<<batch, qc::NT, qc::SMEM_BYTES>>>(x, prx, pry, prz, pent, out);
}

// round 2
// speedup vs baseline: 1.1879x; 1.1879x over previous
#include <cuda_runtime.h>

namespace qc {

constexpr int NQ = 14;
constexpr int NL = 4;
constexpr int NS = 1 << NQ;       // 16384 amplitudes
constexpr int NT = 512;
constexpr int NC = NQ - 1;
constexpr int NWARP = NT / 32;

// shared memory layout (float offsets)
constexpr int OFF_IM  = NS;
constexpr int OFF_U   = 2 * NS;                    // 56 gates * 8 floats
constexpr int OFF_EP  = OFF_U + NL * NQ * 8;       // 52 phases p
constexpr int OFF_EQ  = OFF_EP + NL * NC * 2;      // 52 phases q
constexpr int OFF_ENC = OFF_EQ + NL * NC * 2;      // 14 (c,s) pairs
constexpr int OFF_RED = OFF_ENC + 2 * NQ;
constexpr int SMEM_FLOATS = OFF_RED + NWARP * NQ;
constexpr int SMEM_BYTES  = SMEM_FLOATS * 4;

// XOR swizzle: conflict-free for all sweep group-bases used (S in {0,3,6,9,10})
__device__ __forceinline__ int swz(int i) { return i ^ ((i >> 4) & 31); }

// Fused sweep over bits S..S+W-1:
//   1q gates on local bits G0..W-1   (global qubits S+G0 .. S+W-1)
//   then CNOT(S+st, S+st+1)+RZ for st in C0..W-2, ascending (chain order)
// INIT: instead of loading the state, synthesize the RY-encoded product state.
template<int S, int W, int G0, int C0, bool INIT>
__device__ __forceinline__ void sweepFused(float* __restrict__ re, float* __restrict__ im,
                                           const float* __restrict__ ul,  // 14*8 gate floats (this layer)
                                           const float* __restrict__ pl,  // 13*2 phase floats
                                           const float* __restrict__ ql,
                                           const float* __restrict__ enc, // 14*2 (c,s)
                                           int tid) {
  constexpr int M  = 1 << W;
  constexpr int NG = W - G0;
  float u[NG][8];
#pragma unroll
  for (int j = 0; j < NG; ++j)
#pragma unroll
    for (int e = 0; e < 8; ++e) u[j][e] = ul[(S + G0 + j) * 8 + e];

  float pp[W - 1][2], qq[W - 1][2];
#pragma unroll
  for (int st = C0; st < W - 1; ++st) {
    pp[st][0] = pl[(S + st) * 2]; pp[st][1] = pl[(S + st) * 2 + 1];
    qq[st][0] = ql[(S + st) * 2]; qq[st][1] = ql[(S + st) * 2 + 1];
  }

#pragma unroll
  for (int it = 0; it < (NS >> W) / NT; ++it) {
    const int g = tid + it * NT;
    const int base = ((g >> S) << (S + W)) | (g & ((1 << S) - 1));
    float vr[M], vi[M];

    if (INIT) {
      // product state: amp(idx) = prod_i (bit_i ? s_i : c_i); bits S..S+W-1 are in o
      float T = 1.0f;
#pragma unroll
      for (int i = W; i < NQ; ++i)
        T *= ((base >> i) & 1) ? enc[2 * i + 1] : enc[2 * i];
#pragma unroll
      for (int o = 0; o < M; ++o) {
        float p = T;
#pragma unroll
        for (int i = 0; i < W; ++i)
          p *= ((o >> i) & 1) ? enc[2 * i + 1] : enc[2 * i];
        vr[o] = p; vi[o] = 0.0f;
      }
    } else {
#pragma unroll
      for (int o = 0; o < M; ++o) {
        const int p = swz(base | (o << S));
        vr[o] = re[p]; vi[o] = im[p];
      }
    }

    // 1q gates (distinct bits -> mutually commuting)
#pragma unroll
    for (int j = 0; j < NG; ++j) {
      const int lb = G0 + j;
#pragma unroll
      for (int o = 0; o < M; ++o) {
        if (o & (1 << lb)) continue;
        const int o1 = o | (1 << lb);
        const float ar = vr[o], ai = vi[o], br = vr[o1], bi = vi[o1];
        vr[o]  = u[j][0]*ar - u[j][1]*ai + u[j][2]*br - u[j][3]*bi;
        vi[o]  = u[j][0]*ai + u[j][1]*ar + u[j][2]*bi + u[j][3]*br;
        vr[o1] = u[j][4]*ar - u[j][5]*ai + u[j][6]*br - u[j][7]*bi;
        vi[o1] = u[j][4]*ai + u[j][5]*ar + u[j][6]*bi + u[j][7]*br;
      }
    }

    // CNOT chain + RZ on target (ascending st = chain order)
#pragma unroll
    for (int st = C0; st < W - 1; ++st) {
      const int tb = st + 1;
#pragma unroll
      for (int o = 0; o < M; ++o) {
        if (o & (1 << tb)) continue;
        const int o1 = o | (1 << tb);
        const bool ctrl = (o >> st) & 1;
        float ar, ai, br, bi;
        if (ctrl) { ar = vr[o1]; ai = vi[o1]; br = vr[o];  bi = vi[o];  }
        else      { ar = vr[o];  ai = vi[o];  br = vr[o1]; bi = vi[o1]; }
        vr[o]  = pp[st][0]*ar - pp[st][1]*ai;
        vi[o]  = pp[st][0]*ai + pp[st][1]*ar;
        vr[o1] = qq[st][0]*br - qq[st][1]*bi;
        vi[o1] = qq[st][0]*bi + qq[st][1]*br;
      }
    }

#pragma unroll
    for (int o = 0; o < M; ++o) {
      const int p = swz(base | (o << S));
      re[p] = vr[o]; im[p] = vi[o];
    }
  }
}

__global__ void __launch_bounds__(NT, 1)
qc_kernel(const float* __restrict__ x, const float* __restrict__ prx,
          const float* __restrict__ pry, const float* __restrict__ prz,
          const float* __restrict__ pent, float* __restrict__ out) {
  extern __shared__ float sm[];
  float* re = sm;
  float* im = sm + OFF_IM;
  const float* enc = sm + OFF_ENC;
  const int tid = threadIdx.x;
  const int b = blockIdx.x;

  // ---- prologue: fused U = Rz*Ry*Rx, entangle RZ phases, RY-encoding factors ----
  if (tid < NL * NQ) {
    float cx, sx, cy, sy, cz, sz;
    sincosf(0.5f * prx[tid], &sx, &cx);
    sincosf(0.5f * pry[tid], &sy, &cy);
    sincosf(0.5f * prz[tid], &sz, &cz);
    const float r00x =  cy*cx, r00y =  sy*sx;
    const float r01x = -sy*cx, r01y = -cy*sx;
    const float r10x =  sy*cx, r10y = -cy*sx;
    const float r11x =  cy*cx, r11y = -sy*sx;
    float* u = sm + OFF_U + tid * 8;
    u[0] = r00x*cz + r00y*sz;  u[1] = r00y*cz - r00x*sz;
    u[2] = r01x*cz + r01y*sz;  u[3] = r01y*cz - r01x*sz;
    u[4] = r10x*cz - r10y*sz;  u[5] = r10x*sz + r10y*cz;
    u[6] = r11x*cz - r11y*sz;  u[7] = r11x*sz + r11y*cz;
  }
  if (tid >= 64 && tid < 64 + NL * NC) {
    const int e = tid - 64;
    float c, s; sincosf(0.5f * pent[e], &s, &c);
    sm[OFF_EP + 2*e] = c; sm[OFF_EP + 2*e + 1] = -s;   // e^{-i t/2}
    sm[OFF_EQ + 2*e] = c; sm[OFF_EQ + 2*e + 1] =  s;   // e^{+i t/2}
  }
  if (tid >= 128 && tid < 128 + NQ) {
    const int i = tid - 128;
    const float th = 0.5f * 3.14159265358979323846f * tanhf(x[b * NQ + i]);
    float c, s; sincosf(th, &s, &c);
    sm[OFF_ENC + 2*i] = c; sm[OFF_ENC + 2*i + 1] = s;
  }
  __syncthreads();

  // ---- layers: 5 fused sweeps each; layer-0 sweep-1 synthesizes the init state ----
  for (int l = 0; l < NL; ++l) {
    const float* ul = sm + OFF_U  + l * NQ * 8;
    const float* pl = sm + OFF_EP + l * NC * 2;
    const float* ql = sm + OFF_EQ + l * NC * 2;
    if (l == 0) {
      sweepFused<0, 4, 0, 0, true >(re, im, ul, pl, ql, enc, tid);
    } else {
      __syncthreads();
      sweepFused<0, 4, 0, 0, false>(re, im, ul, pl, ql, enc, tid);
    }
    __syncthreads(); sweepFused<3,  4, 1, 0, false>(re, im, ul, pl, ql, enc, tid);
    __syncthreads(); sweepFused<6,  4, 1, 0, false>(re, im, ul, pl, ql, enc, tid);
    __syncthreads(); sweepFused<9,  4, 1, 0, false>(re, im, ul, pl, ql, enc, tid);
    __syncthreads(); sweepFused<10, 4, 3, 2, false>(re, im, ul, pl, ql, enc, tid);
  }
  __syncthreads();

  // ---- measurement: <Z_q> = sum prob * (1 - 2*bit_q) ----
  float acc[NQ];
#pragma unroll
  for (int q = 0; q < NQ; ++q) acc[q] = 0.0f;
#pragma unroll
  for (int k = 0; k < NS / NT; ++k) {
    const int idx = tid + k * NT;
    const int p = swz(idx);
    const float rr = re[p], ii = im[p];
    const float pr = rr * rr + ii * ii;
#pragma unroll
    for (int q = 0; q < NQ; ++q) {
      if (idx & (1 << q)) acc[q] -= pr; else acc[q] += pr;
    }
  }
#pragma unroll
  for (int q = 0; q < NQ; ++q)
#pragma unroll
    for (int off = 16; off > 0; off >>= 1)
      acc[q] += __shfl_xor_sync(0xffffffffu, acc[q], off);
  const int warp = tid >> 5, lane = tid & 31;
  if (lane == 0) {
#pragma unroll
    for (int q = 0; q < NQ; ++q) sm[OFF_RED + warp * NQ + q] = acc[q];
  }
  __syncthreads();
  if (tid < NQ) {
    float s = 0.0f;
#pragma unroll
    for (int w = 0; w < NWARP; ++w) s += sm[OFF_RED + w * NQ + tid];
    out[b * NQ + tid] = s;
  }
}

} // namespace qc

extern "C" void kernel_launch(void* const* d_in, const int* in_sizes, int n_in,
                              void* d_out, int out_size) {
  const float* x    = (const float*)d_in[0];
  const float* prx  = (const float*)d_in[1];
  const float* pry  = (const float*)d_in[2];
  const float* prz  = (const float*)d_in[3];
  const float* pent = (const float*)d_in[4];
  float* out = (float*)d_out;
  const int batch = in_sizes[0] / qc::NQ;   // 128
  cudaFuncSetAttribute(qc::qc_kernel, cudaFuncAttributeMaxDynamicSharedMemorySize,
                       qc::SMEM_BYTES);
  qc::qc_kernel<<<batch, qc::NT, qc::SMEM_BYTES>>>(x, prx, pry, prz, pent, out);
}

// round 3
// speedup vs baseline: 1.2212x; 1.0280x over previous
#include <cuda_runtime.h>

namespace qc {

typedef unsigned long long ull;

constexpr int NQ = 14;
constexpr int NL = 4;
constexpr int NS = 1 << NQ;       // 16384 amplitudes
constexpr int NT = 512;
constexpr int NC = NQ - 1;
constexpr int NWARP = NT / 32;

// shared memory layout (float offsets)
constexpr int OFF_IM  = NS;
constexpr int OFF_U   = 2 * NS;                     // 56 gates * 12 float2 packs
constexpr int OFF_EP  = OFF_U + NL * NQ * 24;       // 52 steps * 6 float2 packs
constexpr int OFF_ENC = OFF_EP + NL * NC * 12;      // 14 (c,s) pairs
constexpr int OFF_RED = OFF_ENC + 2 * NQ;
constexpr int SMEM_FLOATS = OFF_RED + NWARP * NQ;
constexpr int SMEM_BYTES  = SMEM_FLOATS * 4;

// XOR swizzle: conflict-free for all sweep bases used (S in {0,3,6,9,10})
__device__ __forceinline__ int swz(int i) { return i ^ ((i >> 4) & 31); }

// ---- packed f32x2 helpers (FFMA2 path, sm_100+) ----
__device__ __forceinline__ ull fma2(ull a, ull b, ull c) {
  ull d; asm("fma.rn.f32x2 %0, %1, %2, %3;" : "=l"(d) : "l"(a), "l"(b), "l"(c)); return d;
}
__device__ __forceinline__ ull mul2(ull a, ull b) {
  ull d; asm("mul.rn.f32x2 %0, %1, %2;" : "=l"(d) : "l"(a), "l"(b)); return d;
}
__device__ __forceinline__ ull pk(float lo, float hi) {
  ull d; asm("mov.b64 %0, {%1, %2};" : "=l"(d) : "f"(lo), "f"(hi)); return d;
}
__device__ __forceinline__ void upk(ull a, float& lo, float& hi) {
  asm("mov.b64 {%0, %1}, %2;" : "=f"(lo), "=f"(hi) : "l"(a));
}

// Fused sweep over bits S..S+W-1 (same circuit order as round 2, now packed
// across the thread's two groups g0=tid, g1=tid+NT: identical coefficients).
//   1q gates on local bits G0..W-1, then CNOT(S+st,S+st+1)+RZ for st=C0..W-2.
template<int S, int W, int G0, int C0, bool INIT>
__device__ __forceinline__ void sweepFused(float* __restrict__ re, float* __restrict__ im,
                                           const float* __restrict__ gp,   // gate packs (this layer)
                                           const float* __restrict__ php,  // phase packs (this layer)
                                           const float* __restrict__ enc,  // 14 (c,s)
                                           int tid) {
  constexpr int M = 1 << W;
  const int g0 = tid, g1 = tid + NT;
  const int b0 = ((g0 >> S) << (S + W)) | (g0 & ((1 << S) - 1));
  const int b1 = ((g1 >> S) << (S + W)) | (g1 & ((1 << S) - 1));
  ull VR[M], VI[M];

  if (INIT) {
    float T0 = 1.0f, T1 = 1.0f;
#pragma unroll
    for (int i = W; i < NQ; ++i) {
      T0 *= ((b0 >> i) & 1) ? enc[2 * i + 1] : enc[2 * i];
      T1 *= ((b1 >> i) & 1) ? enc[2 * i + 1] : enc[2 * i];
    }
#pragma unroll
    for (int o = 0; o < M; ++o) {
      float p0 = T0, p1 = T1;
#pragma unroll
      for (int i = 0; i < W; ++i) {
        const float f = ((o >> i) & 1) ? enc[2 * i + 1] : enc[2 * i];
        p0 *= f; p1 *= f;
      }
      VR[o] = pk(p0, p1); VI[o] = pk(0.0f, 0.0f);
    }
  } else {
#pragma unroll
    for (int o = 0; o < M; ++o) {
      const int q0 = swz(b0 | (o << S));
      const int q1 = swz(b1 | (o << S));
      VR[o] = pk(re[q0], re[q1]);
      VI[o] = pk(im[q0], im[q1]);
    }
  }

  // 1q gates: per pair, 16 packed ops cover both groups
#pragma unroll
  for (int j = G0; j < W; ++j) {
    const ull* cp = reinterpret_cast<const ull*>(gp + (S + j) * 24);
    const ull u0 = cp[0], u1 = cp[1], nu1 = cp[2], u2 = cp[3], u3 = cp[4], nu3 = cp[5];
    const ull u4 = cp[6], u5 = cp[7], nu5 = cp[8], u6 = cp[9], u7 = cp[10], nu7 = cp[11];
#pragma unroll
    for (int o = 0; o < M; ++o) {
      if (o & (1 << j)) continue;
      const int o1 = o | (1 << j);
      const ull A = VR[o], B = VI[o], C = VR[o1], D = VI[o1];
      VR[o]  = fma2(nu3, D, fma2(u2, C, fma2(nu1, B, mul2(u0, A))));
      VI[o]  = fma2(u3,  C, fma2(u2, D, fma2(u1,  A, mul2(u0, B))));
      VR[o1] = fma2(nu7, D, fma2(u6, C, fma2(nu5, B, mul2(u4, A))));
      VI[o1] = fma2(u7,  C, fma2(u6, D, fma2(u5,  A, mul2(u4, B))));
    }
  }

  // CNOT chain + RZ on target (ascending st = chain order)
#pragma unroll
  for (int st = C0; st < W - 1; ++st) {
    const int tb = st + 1;
    const ull* pp = reinterpret_cast<const ull*>(php + (S + st) * 12);
    const ull P0 = pp[0], P1 = pp[1], nP1 = pp[2], Q0 = pp[3], Q1 = pp[4], nQ1 = pp[5];
#pragma unroll
    for (int o = 0; o < M; ++o) {
      if (o & (1 << tb)) continue;
      const int o1 = o | (1 << tb);
      const bool ctrl = (o >> st) & 1;
      ull ar, ai, br, bi;
      if (ctrl) { ar = VR[o1]; ai = VI[o1]; br = VR[o];  bi = VI[o];  }
      else      { ar = VR[o];  ai = VI[o];  br = VR[o1]; bi = VI[o1]; }
      VR[o]  = fma2(nP1, ai, mul2(P0, ar));
      VI[o]  = fma2(P1,  ar, mul2(P0, ai));
      VR[o1] = fma2(nQ1, bi, mul2(Q0, br));
      VI[o1] = fma2(Q1,  br, mul2(Q0, bi));
    }
  }

#pragma unroll
  for (int o = 0; o < M; ++o) {
    const int q0 = swz(b0 | (o << S));
    const int q1 = swz(b1 | (o << S));
    float lo, hi;
    upk(VR[o], lo, hi); re[q0] = lo; re[q1] = hi;
    upk(VI[o], lo, hi); im[q0] = lo; im[q1] = hi;
  }
}

__global__ void __launch_bounds__(NT, 1)
qc_kernel(const float* __restrict__ x, const float* __restrict__ prx,
          const float* __restrict__ pry, const float* __restrict__ prz,
          const float* __restrict__ pent, float* __restrict__ out) {
  extern __shared__ float sm[];
  float* re = sm;
  float* im = sm + OFF_IM;
  const float* enc = sm + OFF_ENC;
  const int tid = threadIdx.x;
  const int b = blockIdx.x;

  // ---- prologue: fused U = Rz*Ry*Rx as duplicated/sign-baked f32x2 packs ----
  if (tid < NL * NQ) {
    float cx, sx, cy, sy, cz, sz;
    sincosf(0.5f * prx[tid], &sx, &cx);
    sincosf(0.5f * pry[tid], &sy, &cy);
    sincosf(0.5f * prz[tid], &sz, &cz);
    const float r00x =  cy*cx, r00y =  sy*sx;
    const float r01x = -sy*cx, r01y = -cy*sx;
    const float r10x =  sy*cx, r10y = -cy*sx;
    const float r11x =  cy*cx, r11y = -sy*sx;
    const float u0 = r00x*cz + r00y*sz, u1 = r00y*cz - r00x*sz;
    const float u2 = r01x*cz + r01y*sz, u3 = r01y*cz - r01x*sz;
    const float u4 = r10x*cz - r10y*sz, u5 = r10x*sz + r10y*cz;
    const float u6 = r11x*cz - r11y*sz, u7 = r11x*sz + r11y*cz;
    float2* g2 = reinterpret_cast<float2*>(sm + OFF_U) + tid * 12;
    g2[0]  = make_float2(u0, u0);   g2[1]  = make_float2(u1, u1);
    g2[2]  = make_float2(-u1, -u1); g2[3]  = make_float2(u2, u2);
    g2[4]  = make_float2(u3, u3);   g2[5]  = make_float2(-u3, -u3);
    g2[6]  = make_float2(u4, u4);   g2[7]  = make_float2(u5, u5);
    g2[8]  = make_float2(-u5, -u5); g2[9]  = make_float2(u6, u6);
    g2[10] = make_float2(u7, u7);   g2[11] = make_float2(-u7, -u7);
  }
  if (tid >= 64 && tid < 64 + NL * NC) {
    const int e = tid - 64;
    float c, s; sincosf(0.5f * pent[e], &s, &c);
    // p = e^{-i t/2} = (c, -s); q = e^{+i t/2} = (c, s)
    float2* p2 = reinterpret_cast<float2*>(sm + OFF_EP) + e * 6;
    p2[0] = make_float2(c, c);    // P0
    p2[1] = make_float2(-s, -s);  // P1
    p2[2] = make_float2(s, s);    // -P1
    p2[3] = make_float2(c, c);    // Q0
    p2[4] = make_float2(s, s);    // Q1
    p2[5] = make_float2(-s, -s);  // -Q1
  }
  if (tid >= 128 && tid < 128 + NQ) {
    const int i = tid - 128;
    const float th = 0.5f * 3.14159265358979323846f * tanhf(x[b * NQ + i]);
    float c, s; sincosf(th, &s, &c);
    sm[OFF_ENC + 2*i] = c; sm[OFF_ENC + 2*i + 1] = s;
  }
  __syncthreads();

  // ---- layers: 5 fused packed sweeps; layer-0 sweep-1 synthesizes init state ----
  for (int l = 0; l < NL; ++l) {
    const float* gp  = sm + OFF_U  + l * NQ * 24;
    const float* php = sm + OFF_EP + l * NC * 12;
    if (l == 0) {
      sweepFused<0, 4, 0, 0, true >(re, im, gp, php, enc, tid);
    } else {
      __syncthreads();
      sweepFused<0, 4, 0, 0, false>(re, im, gp, php, enc, tid);
    }
    __syncthreads(); sweepFused<3,  4, 1, 0, false>(re, im, gp, php, enc, tid);
    __syncthreads(); sweepFused<6,  4, 1, 0, false>(re, im, gp, php, enc, tid);
    __syncthreads(); sweepFused<9,  4, 1, 0, false>(re, im, gp, php, enc, tid);
    __syncthreads(); sweepFused<10, 4, 3, 2, false>(re, im, gp, php, enc, tid);
  }
  __syncthreads();

  // ---- measurement: <Z_q> = sum prob * (1 - 2*bit_q) ----
  float acc[NQ];
#pragma unroll
  for (int q = 0; q < NQ; ++q) acc[q] = 0.0f;
#pragma unroll
  for (int k = 0; k < NS / NT; ++k) {
    const int idx = tid + k * NT;
    const int p = swz(idx);
    const float rr = re[p], ii = im[p];
    const float pr = rr * rr + ii * ii;
#pragma unroll
    for (int q = 0; q < NQ; ++q) {
      if (idx & (1 << q)) acc[q] -= pr; else acc[q] += pr;
    }
  }
#pragma unroll
  for (int q = 0; q < NQ; ++q)
#pragma unroll
    for (int off = 16; off > 0; off >>= 1)
      acc[q] += __shfl_xor_sync(0xffffffffu, acc[q], off);
  const int warp = tid >> 5, lane = tid & 31;
  if (lane == 0) {
#pragma unroll
    for (int q = 0; q < NQ; ++q) sm[OFF_RED + warp * NQ + q] = acc[q];
  }
  __syncthreads();
  if (tid < NQ) {
    float s = 0.0f;
#pragma unroll
    for (int w = 0; w < NWARP; ++w) s += sm[OFF_RED + w * NQ + tid];
    out[b * NQ + tid] = s;
  }
}

} // namespace qc

extern "C" void kernel_launch(void* const* d_in, const int* in_sizes, int n_in,
                              void* d_out, int out_size) {
  const float* x    = (const float*)d_in[0];
  const float* prx  = (const float*)d_in[1];
  const float* pry  = (const float*)d_in[2];
  const float* prz  = (const float*)d_in[3];
  const float* pent = (const float*)d_in[4];
  float* out = (float*)d_out;
  const int batch = in_sizes[0] / qc::NQ;   // 128
  cudaFuncSetAttribute(qc::qc_kernel, cudaFuncAttributeMaxDynamicSharedMemorySize,
                       qc::SMEM_BYTES);
  qc::qc_kernel<<<batch, qc::NT, qc::SMEM_BYTES>>>(x, prx, pry, prz, pent, out);
}